// round 9
// baseline (speedup 1.0000x reference)
#include <cuda_runtime.h>
#include <math.h>

#define NCLS   80
#define CH     85
#define NBOX   70
#define NBATCH 16
#define CPB    256
#define INV_IN2 (1.0f/(608.0f*608.0f))

#define CELLS_S (NBATCH*76*76*3)   // 277248
#define CELLS_M (NBATCH*38*38*3)   //  69312
#define CELLS_L (NBATCH*19*19*3)   //  17328
#define BLKS_S  ((CELLS_S + CPB - 1) / CPB)   // 1083
#define BLKS_M  ((CELLS_M + CPB - 1) / CPB)   //  271
#define BLKS_L  ((CELLS_L + CPB - 1) / CPB)   //   68
#define NBLK    (BLKS_S + BLKS_M + BLKS_L)    // 1422

__device__ double   g_acc[3];
__device__ unsigned g_count;

__constant__ float c_anch[3][6] = {
    { 12.f,  16.f,  19.f,  36.f,  40.f,  28.f},
    { 36.f,  75.f,  76.f,  55.f,  72.f, 146.f},
    {142.f, 110.f, 192.f, 243.f, 459.f, 401.f}
};

__device__ __forceinline__ float ex2(float x) {
    float r; asm("ex2.approx.ftz.f32 %0, %1;" : "=f"(r) : "f"(x)); return r;
}
__device__ __forceinline__ float lg2(float x) {
    float r; asm("lg2.approx.ftz.f32 %0, %1;" : "=f"(r) : "f"(x)); return r;
}
#define L2E 1.4426950408889634f
#define LN2 0.6931471805599453f

__device__ __forceinline__ float softplusf(float x) {
    return fmaxf(x, 0.f) + LN2 * lg2(1.f + ex2(-fabsf(x) * L2E));
}
__device__ __forceinline__ float sigmoidf(float x) {
    return __fdividef(1.f, 1.f + ex2(-x * L2E));
}

struct Smem {
    float4 box [NBATCH*NBOX];
    float  ar  [NBATCH*NBOX];
    float  resp[CPB];
    float  rbuf[3][CPB/32];
};

// branchless: h0..h4 = v[off..off+4]  (off in 0..3)
__device__ __forceinline__ void extract5_sel(
    float4 A, float4 B, int off,
    float& h0, float& h1, float& h2, float& h3, float& h4)
{
    float v0=A.x, v1=A.y, v2=A.z, v3=A.w, v4=B.x, v5=B.y, v6=B.z, v7=B.w;
    bool hi  = (off >= 2);
    bool odd = (off & 1);
    h0 = hi ? (odd ? v3 : v2) : (odd ? v1 : v0);
    h1 = hi ? (odd ? v4 : v3) : (odd ? v2 : v1);
    h2 = hi ? (odd ? v5 : v4) : (odd ? v3 : v2);
    h3 = hi ? (odd ? v6 : v5) : (odd ? v4 : v3);
    h4 = hi ? (odd ? v7 : v6) : (odd ? v5 : v4);
}

template<int S, int STRIDE, int SCALE, int NCELL>
__device__ __forceinline__ void process_scale(
    const float* __restrict__ conv,
    const float* __restrict__ label,
    Smem* sm, int sblk, float& tc, float& tf, float& ps)
{
    const int tid      = threadIdx.x;
    const int cellBase = sblk * CPB;
    const int cells    = min(CPB, NCELL - cellBase);
    const bool active  = (tid < cells);

    const float4* __restrict__ cv4g = reinterpret_cast<const float4*>(conv);
    const float4* __restrict__ lb4g = reinterpret_cast<const float4*>(label);

    // ===== Head load (vectorized, issued up-front; warms L2/L1 for phase 1) =====
    float dx=0.f, dy=0.f, dw=0.f, dh=0.f, dc=0.f;
    float lx=0.f, ly=0.f, lw=0.f, lh=0.f, resp=0.f;
    if (active) {
        const size_t f0 = (size_t)(cellBase + tid) * CH;
        const size_t q  = f0 >> 2;
        const int  off  = (int)(f0 & 3);
        float4 a0 = __ldg(cv4g + q), a1 = __ldg(cv4g + q + 1);
        float4 b0 = __ldg(lb4g + q), b1 = __ldg(lb4g + q + 1);
        extract5_sel(a0, a1, off, dx, dy, dw, dh, dc);
        extract5_sel(b0, b1, off, lx, ly, lw, lh, resp);
        sm->resp[tid] = resp;
    }
    __syncthreads();

    // ===== Phase 2 FIRST: per-cell ciou + conf + head-BCE correction =====
    if (active) {
        const int idx = cellBase + tid;
        int a = idx % 3;
        int r = idx / 3;
        int j = r % S; r /= S;
        int i = r % S;
        int b = r / S;

        // phase 1 will include head channels k..4 of this cell (alignment-
        // determined, k = (4 - (cell%4)) & 3; cell%4 == tid%4 here) with this
        // cell's resp; subtract exactly those contributions from registers.
        {
            int k = (4 - (tid & 3)) & 3;   // 0..3, so ch 3,4 always included
            float sub = (softplusf(dh) - lh * dh)
                      + (softplusf(dc) - resp * dc);
            if (k <= 2) sub += softplusf(dw) - lw * dw;
            if (k <= 1) sub += softplusf(dy) - ly * dy;
            if (k == 0) sub += softplusf(dx) - lx * dx;
            ps -= resp * sub;
        }

        float aw = c_anch[SCALE][a*2 + 0];
        float ah = c_anch[SCALE][a*2 + 1];

        float px = (sigmoidf(dx) + (float)j) * (float)STRIDE;
        float py = (sigmoidf(dy) + (float)i) * (float)STRIDE;
        float pw = ex2(dw * L2E) * aw;
        float ph = ex2(dh * L2E) * ah;

        float px1 = px - 0.5f*pw, py1 = py - 0.5f*ph;
        float px2 = px + 0.5f*pw, py2 = py + 0.5f*ph;
        float lx1 = lx - 0.5f*lw, ly1 = ly - 0.5f*lh;
        float lx2 = lx + 0.5f*lw, ly2 = ly + 0.5f*lh;

        float areap = (px2 - px1) * (py2 - py1);
        float areal = (lx2 - lx1) * (ly2 - ly1);
        float iw = fmaxf(fminf(px2, lx2) - fmaxf(px1, lx1), 0.f);
        float ih = fmaxf(fminf(py2, ly2) - fmaxf(py1, ly1), 0.f);
        float inter = iw * ih;
        float uni   = areap + areal - inter;
        float iou   = __fdividef(inter, uni + 1e-9f);

        float ew = fmaxf(px2, lx2) - fminf(px1, lx1);
        float eh = fmaxf(py2, ly2) - fminf(py1, ly1);
        float c2 = ew*ew + eh*eh;
        float ddx = px - lx, ddy = py - ly;
        float p2 = ddx*ddx + ddy*ddy;

        const float FOUR_OVER_PI2 = 0.40528473456935109f;
        float at = atanf(__fdividef(pw, ph + 1e-9f)) -
                   atanf(__fdividef(lw, lh + 1e-9f));
        float v     = FOUR_OVER_PI2 * at * at;
        float alpha = __fdividef(v, 1.f - iou + v);
        float ciou  = iou - __fdividef(p2, c2) - alpha * v;

        tc = resp * (2.f - lw*lh*INV_IN2) * (1.f - ciou);

        float pa = pw * ph;
        const float4* bptr = sm->box + b * NBOX;
        const float*  aptr = sm->ar  + b * NBOX;
        float m = -1e30f;
        #pragma unroll 5
        for (int k = 0; k < NBOX; k++) {
            float4 bx = bptr[k];
            float bw = fmaxf(fminf(px2, bx.z) - fmaxf(px1, bx.x), 0.f);
            float bh = fmaxf(fminf(py2, bx.w) - fmaxf(py1, bx.y), 0.f);
            m = fmaxf(m, __fmaf_rn(3.f, bw * bh, -aptr[k]));
        }

        float spc = softplusf(dc);
        tf = resp * (spc - dc);
        if (m < pa) tf += (1.f - resp) * spc;
    }

    // ===== Phase 1: coalesced float4 stream; no lower mask, wrap-drop only =====
    const float4* __restrict__ cv4 = cv4g + (size_t)cellBase * CH / 4;
    const float4* __restrict__ lb4 = lb4g + (size_t)cellBase * CH / 4;
    const int nf4 = cells * CH / 4;

    #pragma unroll 4
    for (int t = tid; t < nf4; t += CPB) {
        const int e  = 4 * t;
        const int cl = e / CH;
        const int c0 = e - cl * CH;          // comp i wrapped iff c0 + i >= 85

        float4 x  = __ldg(cv4 + t);
        float4 lp = __ldg(lb4 + t);
        float  rsp = sm->resp[cl];

        bool w1 = (c0 < 84), w2 = (c0 < 83), w3 = (c0 < 82);

        float t0 = ex2(x.x * L2E);
        float t1 = w1 ? ex2(x.y * L2E) : 0.f;
        float t2 = w2 ? ex2(x.z * L2E) : 0.f;
        float t3 = w3 ? ex2(x.w * L2E) : 0.f;

        float p = (1.f + t0) * (1.f + t1) * (1.f + t2) * (1.f + t3);

        float dot = lp.x * x.x
                  + (w1 ? lp.y : 0.f) * x.y
                  + (w2 ? lp.z : 0.f) * x.z
                  + (w3 ? lp.w : 0.f) * x.w;

        ps += rsp * (LN2 * lg2(p) - dot);
    }
}

__global__ void __launch_bounds__(CPB, 6)
yolo_fused_kernel(const float* __restrict__ conv_s, const float* __restrict__ lab_s,
                  const float* __restrict__ conv_m, const float* __restrict__ lab_m,
                  const float* __restrict__ conv_l, const float* __restrict__ lab_l,
                  const float* __restrict__ bboxes, float* __restrict__ out)
{
    __shared__ Smem sm;

    const int tid = threadIdx.x;

    for (int t = tid; t < NBATCH*NBOX; t += CPB) {
        float4 v = __ldg(reinterpret_cast<const float4*>(bboxes) + t);
        sm.box[t] = make_float4(v.x - 0.5f*v.z, v.y - 0.5f*v.w,
                                v.x + 0.5f*v.z, v.y + 0.5f*v.w);
        sm.ar[t]  = v.z * v.w;
    }
    // NOTE: __syncthreads happens inside process_scale (after head load)

    float tc = 0.f, tf = 0.f, ps = 0.f;

    const int blk = blockIdx.x;
    if (blk < BLKS_S) {
        process_scale<76,  8, 0, CELLS_S>(conv_s, lab_s, &sm, blk, tc, tf, ps);
    } else if (blk < BLKS_S + BLKS_M) {
        process_scale<38, 16, 1, CELLS_M>(conv_m, lab_m, &sm, blk - BLKS_S, tc, tf, ps);
    } else {
        process_scale<19, 32, 2, CELLS_L>(conv_l, lab_l, &sm, blk - BLKS_S - BLKS_M, tc, tf, ps);
    }

    // block reduction + device-wide finalize
    const unsigned mask = 0xffffffffu;
    #pragma unroll
    for (int off = 16; off; off >>= 1) {
        tc += __shfl_down_sync(mask, tc, off);
        tf += __shfl_down_sync(mask, tf, off);
        ps += __shfl_down_sync(mask, ps, off);
    }
    int wid = tid >> 5, lane = tid & 31;
    if (lane == 0) { sm.rbuf[0][wid] = tc; sm.rbuf[1][wid] = tf; sm.rbuf[2][wid] = ps; }
    __syncthreads();

    if (tid == 0) {
        float sc = 0.f, sf = 0.f, sp = 0.f;
        #pragma unroll
        for (int w = 0; w < CPB/32; w++) {
            sc += sm.rbuf[0][w]; sf += sm.rbuf[1][w]; sp += sm.rbuf[2][w];
        }
        atomicAdd(&g_acc[0], (double)sc);
        atomicAdd(&g_acc[1], (double)sf);
        atomicAdd(&g_acc[2], (double)sp);

        __threadfence();
        unsigned old = atomicInc(&g_count, NBLK - 1);
        if (old == NBLK - 1) {
            double ci = atomicAdd(&g_acc[0], 0.0) * (1.0 / NBATCH);
            double cf = atomicAdd(&g_acc[1], 0.0) * (1.0 / NBATCH);
            double pr = atomicAdd(&g_acc[2], 0.0) * (1.0 / NBATCH);
            out[0] = (float)(ci + cf + pr);
            out[1] = (float)ci;
            out[2] = (float)cf;
            out[3] = (float)pr;
            atomicExch((unsigned long long*)&g_acc[0], 0ULL);
            atomicExch((unsigned long long*)&g_acc[1], 0ULL);
            atomicExch((unsigned long long*)&g_acc[2], 0ULL);
        }
    }
}

extern "C" void kernel_launch(void* const* d_in, const int* in_sizes, int n_in,
                              void* d_out, int out_size)
{
    const float* conv_l = (const float*)d_in[0];
    const float* conv_m = (const float*)d_in[1];
    const float* conv_s = (const float*)d_in[2];
    const float* lab_s  = (const float*)d_in[3];
    const float* lab_m  = (const float*)d_in[4];
    const float* lab_l  = (const float*)d_in[5];
    const float* bb     = (const float*)d_in[6];

    yolo_fused_kernel<<<NBLK, CPB>>>(conv_s, lab_s, conv_m, lab_m,
                                     conv_l, lab_l, bb, (float*)d_out);
}

// round 10
// speedup vs baseline: 1.0820x; 1.0820x over previous
#include <cuda_runtime.h>
#include <math.h>

#define NCLS   80
#define CH     85
#define NBOX   70
#define NBATCH 16
#define CPB    256
#define INV_IN2 (1.0f/(608.0f*608.0f))

#define CELLS_S (NBATCH*76*76*3)   // 277248
#define CELLS_M (NBATCH*38*38*3)   //  69312
#define CELLS_L (NBATCH*19*19*3)   //  17328
#define BLKS_S  ((CELLS_S + CPB - 1) / CPB)   // 1083
#define BLKS_M  ((CELLS_M + CPB - 1) / CPB)   //  271
#define BLKS_L  ((CELLS_L + CPB - 1) / CPB)   //   68
#define NBLK    (BLKS_S + BLKS_M + BLKS_L)    // 1422

__device__ double   g_acc[3];
__device__ unsigned g_count;

__constant__ float c_anch[3][6] = {
    { 12.f,  16.f,  19.f,  36.f,  40.f,  28.f},
    { 36.f,  75.f,  76.f,  55.f,  72.f, 146.f},
    {142.f, 110.f, 192.f, 243.f, 459.f, 401.f}
};

__device__ __forceinline__ float ex2(float x) {
    float r; asm("ex2.approx.ftz.f32 %0, %1;" : "=f"(r) : "f"(x)); return r;
}
__device__ __forceinline__ float lg2(float x) {
    float r; asm("lg2.approx.ftz.f32 %0, %1;" : "=f"(r) : "f"(x)); return r;
}
#define L2E 1.4426950408889634f
#define LN2 0.6931471805599453f

__device__ __forceinline__ float softplusf(float x) {
    return fmaxf(x, 0.f) + LN2 * lg2(1.f + ex2(-fabsf(x) * L2E));
}
__device__ __forceinline__ float sigmoidf(float x) {
    return __fdividef(1.f, 1.f + ex2(-x * L2E));
}

struct Smem {
    float4 box [NBATCH*NBOX];
    float  ar  [NBATCH*NBOX];
    float4 mask[CH];          // per-c0 component masks (0/1)
    float  resp[CPB];         // label ch4 per local cell
    float  rbuf[3][CPB/32];
};

// branchless: h0..h4 = v[off..off+4]  (off in 0..3)
__device__ __forceinline__ void extract5_sel(
    float4 A, float4 B, int off,
    float& h0, float& h1, float& h2, float& h3, float& h4)
{
    float v0=A.x, v1=A.y, v2=A.z, v3=A.w, v4=B.x, v5=B.y, v6=B.z, v7=B.w;
    bool hi  = (off >= 2);
    bool odd = (off & 1);
    h0 = hi ? (odd ? v3 : v2) : (odd ? v1 : v0);
    h1 = hi ? (odd ? v4 : v3) : (odd ? v2 : v1);
    h2 = hi ? (odd ? v5 : v4) : (odd ? v3 : v2);
    h3 = hi ? (odd ? v6 : v5) : (odd ? v4 : v3);
    h4 = hi ? (odd ? v7 : v6) : (odd ? v5 : v4);
}

template<int S, int STRIDE, int SCALE, int NCELL>
__device__ __forceinline__ void process_scale(
    const float* __restrict__ conv,
    const float* __restrict__ label,
    Smem* sm, int sblk, float& tc, float& tf, float& ps)
{
    const int tid      = threadIdx.x;
    const int cellBase = sblk * CPB;
    const int cells    = min(CPB, NCELL - cellBase);
    const bool active  = (tid < cells);

    const float4* __restrict__ cv4g = reinterpret_cast<const float4*>(conv);
    const float4* __restrict__ lb4g = reinterpret_cast<const float4*>(label);

    // ===== Head load (vectorized, issued up-front; warms L2/L1 for phase 1) =====
    float dx=0.f, dy=0.f, dw=0.f, dh=0.f, dc=0.f;
    float lx=0.f, ly=0.f, lw=0.f, lh=0.f, resp=0.f;
    if (active) {
        const size_t f0 = (size_t)(cellBase + tid) * CH;
        const size_t q  = f0 >> 2;
        const int  off  = (int)(f0 & 3);
        float4 a0 = __ldg(cv4g + q), a1 = __ldg(cv4g + q + 1);
        float4 b0 = __ldg(lb4g + q), b1 = __ldg(lb4g + q + 1);
        extract5_sel(a0, a1, off, dx, dy, dw, dh, dc);
        extract5_sel(b0, b1, off, lx, ly, lw, lh, resp);
        sm->resp[tid] = resp;
    }
    __syncthreads();   // resp + (caller's) box/ar/mask visible

    // ===== Phase 2 FIRST: per-cell ciou + conf from registers =====
    if (active) {
        const int idx = cellBase + tid;
        int a = idx % 3;
        int r = idx / 3;
        int j = r % S; r /= S;
        int i = r % S;
        int b = r / S;

        float aw = c_anch[SCALE][a*2 + 0];
        float ah = c_anch[SCALE][a*2 + 1];

        float px = (sigmoidf(dx) + (float)j) * (float)STRIDE;
        float py = (sigmoidf(dy) + (float)i) * (float)STRIDE;
        float pw = ex2(dw * L2E) * aw;
        float ph = ex2(dh * L2E) * ah;

        float px1 = px - 0.5f*pw, py1 = py - 0.5f*ph;
        float px2 = px + 0.5f*pw, py2 = py + 0.5f*ph;
        float lx1 = lx - 0.5f*lw, ly1 = ly - 0.5f*lh;
        float lx2 = lx + 0.5f*lw, ly2 = ly + 0.5f*lh;

        float areap = (px2 - px1) * (py2 - py1);
        float areal = (lx2 - lx1) * (ly2 - ly1);
        float iw = fmaxf(fminf(px2, lx2) - fmaxf(px1, lx1), 0.f);
        float ih = fmaxf(fminf(py2, ly2) - fmaxf(py1, ly1), 0.f);
        float inter = iw * ih;
        float uni   = areap + areal - inter;
        float iou   = __fdividef(inter, uni + 1e-9f);

        float ew = fmaxf(px2, lx2) - fminf(px1, lx1);
        float eh = fmaxf(py2, ly2) - fminf(py1, ly1);
        float c2 = ew*ew + eh*eh;
        float ddx = px - lx, ddy = py - ly;
        float p2 = ddx*ddx + ddy*ddy;

        const float FOUR_OVER_PI2 = 0.40528473456935109f;
        float at = atanf(__fdividef(pw, ph + 1e-9f)) -
                   atanf(__fdividef(lw, lh + 1e-9f));
        float v     = FOUR_OVER_PI2 * at * at;
        float alpha = __fdividef(v, 1.f - iou + v);
        float ciou  = iou - __fdividef(p2, c2) - alpha * v;

        tc = resp * (2.f - lw*lh*INV_IN2) * (1.f - ciou);

        float pa = pw * ph;
        const float4* bptr = sm->box + b * NBOX;
        const float*  aptr = sm->ar  + b * NBOX;
        float m = -1e30f;
        #pragma unroll 5
        for (int k = 0; k < NBOX; k++) {
            float4 bx = bptr[k];
            float bw = fmaxf(fminf(px2, bx.z) - fmaxf(px1, bx.x), 0.f);
            float bh = fmaxf(fminf(py2, bx.w) - fmaxf(py1, bx.y), 0.f);
            m = fmaxf(m, __fmaf_rn(3.f, bw * bh, -aptr[k]));
        }

        float spc = softplusf(dc);
        tf = resp * (spc - dc);
        if (m < pa) tf += (1.f - resp) * spc;
    }

    // ===== Phase 1: coalesced float4 stream; product-form softplus =====
    const float4* __restrict__ cv4 = cv4g + (size_t)cellBase * CH / 4;
    const float4* __restrict__ lb4 = lb4g + (size_t)cellBase * CH / 4;
    const int nf4 = cells * CH / 4;

    #pragma unroll 4
    for (int t = tid; t < nf4; t += CPB) {
        const int e  = 4 * t;
        const int cl = e / CH;
        const int c0 = e - cl * CH;

        float4 x  = __ldg(cv4 + t);
        float4 lp = __ldg(lb4 + t);
        float4 mk = sm->mask[c0];
        float  rsp = sm->resp[cl];

        float t0 = ex2(x.x * L2E) * mk.x;
        float t1 = ex2(x.y * L2E) * mk.y;
        float t2 = ex2(x.z * L2E) * mk.z;
        float t3 = ex2(x.w * L2E) * mk.w;

        float p = (1.f + t0) * (1.f + t1) * (1.f + t2) * (1.f + t3);

        float dot = (lp.x * mk.x) * x.x
                  + (lp.y * mk.y) * x.y
                  + (lp.z * mk.z) * x.z
                  + (lp.w * mk.w) * x.w;

        ps += rsp * (LN2 * lg2(p) - dot);
    }
}

__global__ void __launch_bounds__(CPB, 6)
yolo_fused_kernel(const float* __restrict__ conv_s, const float* __restrict__ lab_s,
                  const float* __restrict__ conv_m, const float* __restrict__ lab_m,
                  const float* __restrict__ conv_l, const float* __restrict__ lab_l,
                  const float* __restrict__ bboxes, float* __restrict__ out)
{
    __shared__ Smem sm;

    const int tid = threadIdx.x;

    for (int t = tid; t < NBATCH*NBOX; t += CPB) {
        float4 v = __ldg(reinterpret_cast<const float4*>(bboxes) + t);
        sm.box[t] = make_float4(v.x - 0.5f*v.z, v.y - 0.5f*v.w,
                                v.x + 0.5f*v.z, v.y + 0.5f*v.w);
        sm.ar[t]  = v.z * v.w;
    }
    if (tid < CH) {
        int c0 = tid;
        sm.mask[c0] = make_float4(
            (c0 >= 5)              ? 1.f : 0.f,
            (c0 >= 4 && c0 <= 83)  ? 1.f : 0.f,
            (c0 >= 3 && c0 <= 82)  ? 1.f : 0.f,
            (c0 >= 2 && c0 <= 81)  ? 1.f : 0.f);
    }
    // NOTE: __syncthreads happens inside process_scale (after head load)

    float tc = 0.f, tf = 0.f, ps = 0.f;

    const int blk = blockIdx.x;
    if (blk < BLKS_S) {
        process_scale<76,  8, 0, CELLS_S>(conv_s, lab_s, &sm, blk, tc, tf, ps);
    } else if (blk < BLKS_S + BLKS_M) {
        process_scale<38, 16, 1, CELLS_M>(conv_m, lab_m, &sm, blk - BLKS_S, tc, tf, ps);
    } else {
        process_scale<19, 32, 2, CELLS_L>(conv_l, lab_l, &sm, blk - BLKS_S - BLKS_M, tc, tf, ps);
    }

    // block reduction + device-wide finalize
    const unsigned mask = 0xffffffffu;
    #pragma unroll
    for (int off = 16; off; off >>= 1) {
        tc += __shfl_down_sync(mask, tc, off);
        tf += __shfl_down_sync(mask, tf, off);
        ps += __shfl_down_sync(mask, ps, off);
    }
    int wid = tid >> 5, lane = tid & 31;
    if (lane == 0) { sm.rbuf[0][wid] = tc; sm.rbuf[1][wid] = tf; sm.rbuf[2][wid] = ps; }
    __syncthreads();

    if (tid == 0) {
        float sc = 0.f, sf = 0.f, sp = 0.f;
        #pragma unroll
        for (int w = 0; w < CPB/32; w++) {
            sc += sm.rbuf[0][w]; sf += sm.rbuf[1][w]; sp += sm.rbuf[2][w];
        }
        atomicAdd(&g_acc[0], (double)sc);
        atomicAdd(&g_acc[1], (double)sf);
        atomicAdd(&g_acc[2], (double)sp);

        __threadfence();
        unsigned old = atomicInc(&g_count, NBLK - 1);
        if (old == NBLK - 1) {
            double ci = atomicAdd(&g_acc[0], 0.0) * (1.0 / NBATCH);
            double cf = atomicAdd(&g_acc[1], 0.0) * (1.0 / NBATCH);
            double pr = atomicAdd(&g_acc[2], 0.0) * (1.0 / NBATCH);
            out[0] = (float)(ci + cf + pr);
            out[1] = (float)ci;
            out[2] = (float)cf;
            out[3] = (float)pr;
            atomicExch((unsigned long long*)&g_acc[0], 0ULL);
            atomicExch((unsigned long long*)&g_acc[1], 0ULL);
            atomicExch((unsigned long long*)&g_acc[2], 0ULL);
        }
    }
}

extern "C" void kernel_launch(void* const* d_in, const int* in_sizes, int n_in,
                              void* d_out, int out_size)
{
    const float* conv_l = (const float*)d_in[0];
    const float* conv_m = (const float*)d_in[1];
    const float* conv_s = (const float*)d_in[2];
    const float* lab_s  = (const float*)d_in[3];
    const float* lab_m  = (const float*)d_in[4];
    const float* lab_l  = (const float*)d_in[5];
    const float* bb     = (const float*)d_in[6];

    yolo_fused_kernel<<<NBLK, CPB>>>(conv_s, lab_s, conv_m, lab_m,
                                     conv_l, lab_l, bb, (float*)d_out);
}

// round 11
// speedup vs baseline: 1.1392x; 1.0529x over previous
#include <cuda_runtime.h>
#include <math.h>

#define NCLS   80
#define CH     85
#define NBOX   70
#define NBATCH 16
#define CPB    256
#define INV_IN2 (1.0f/(608.0f*608.0f))

#define CELLS_S (NBATCH*76*76*3)   // 277248
#define CELLS_M (NBATCH*38*38*3)   //  69312
#define CELLS_L (NBATCH*19*19*3)   //  17328
#define BLKS_S  ((CELLS_S + CPB - 1) / CPB)   // 1083
#define BLKS_M  ((CELLS_M + CPB - 1) / CPB)   //  271
#define BLKS_L  ((CELLS_L + CPB - 1) / CPB)   //   68
#define NBLK    (BLKS_S + BLKS_M + BLKS_L)    // 1422

__device__ double   g_acc[3];
__device__ unsigned g_count;

__constant__ float c_anch[3][6] = {
    { 12.f,  16.f,  19.f,  36.f,  40.f,  28.f},
    { 36.f,  75.f,  76.f,  55.f,  72.f, 146.f},
    {142.f, 110.f, 192.f, 243.f, 459.f, 401.f}
};

__device__ __forceinline__ float ex2(float x) {
    float r; asm("ex2.approx.ftz.f32 %0, %1;" : "=f"(r) : "f"(x)); return r;
}
__device__ __forceinline__ float lg2(float x) {
    float r; asm("lg2.approx.ftz.f32 %0, %1;" : "=f"(r) : "f"(x)); return r;
}
#define L2E 1.4426950408889634f
#define LN2 0.6931471805599453f

__device__ __forceinline__ float softplusf(float x) {
    return fmaxf(x, 0.f) + LN2 * lg2(1.f + ex2(-fabsf(x) * L2E));
}
__device__ __forceinline__ float sigmoidf(float x) {
    return __fdividef(1.f, 1.f + ex2(-x * L2E));
}

struct Smem {
    float4 box [NBATCH*NBOX];
    float  ar  [NBATCH*NBOX];
    float4 mask[CH];          // per-c0 component masks (0/1)
    float  resp[CPB];         // label ch4 per local cell
    float  rbuf[3][CPB/32];
};

// branchless: h0..h4 = v[off..off+4]  (off in 0..3)
__device__ __forceinline__ void extract5_sel(
    float4 A, float4 B, int off,
    float& h0, float& h1, float& h2, float& h3, float& h4)
{
    float v0=A.x, v1=A.y, v2=A.z, v3=A.w, v4=B.x, v5=B.y, v6=B.z, v7=B.w;
    bool hi  = (off >= 2);
    bool odd = (off & 1);
    h0 = hi ? (odd ? v3 : v2) : (odd ? v1 : v0);
    h1 = hi ? (odd ? v4 : v3) : (odd ? v2 : v1);
    h2 = hi ? (odd ? v5 : v4) : (odd ? v3 : v2);
    h3 = hi ? (odd ? v6 : v5) : (odd ? v4 : v3);
    h4 = hi ? (odd ? v7 : v6) : (odd ? v5 : v4);
}

template<int S, int STRIDE, int SCALE, int NCELL>
__device__ __forceinline__ void process_scale(
    const float* __restrict__ conv,
    const float* __restrict__ label,
    Smem* sm, int sblk, float& tc, float& tf, float& ps)
{
    const int tid      = threadIdx.x;
    const int cellBase = sblk * CPB;
    const int cells    = min(CPB, NCELL - cellBase);
    const bool active  = (tid < cells);

    const float4* __restrict__ cv4g = reinterpret_cast<const float4*>(conv);
    const float4* __restrict__ lb4g = reinterpret_cast<const float4*>(label);

    // ===== Head load (vectorized, issued up-front; warms L2/L1 for phase 1) =====
    float dx=0.f, dy=0.f, dw=0.f, dh=0.f, dc=0.f;
    float lx=0.f, ly=0.f, lw=0.f, lh=0.f, resp=0.f;
    if (active) {
        const size_t f0 = (size_t)(cellBase + tid) * CH;
        const size_t q  = f0 >> 2;
        const int  off  = (int)(f0 & 3);
        float4 a0 = __ldg(cv4g + q), a1 = __ldg(cv4g + q + 1);
        float4 b0 = __ldg(lb4g + q), b1 = __ldg(lb4g + q + 1);
        extract5_sel(a0, a1, off, dx, dy, dw, dh, dc);
        extract5_sel(b0, b1, off, lx, ly, lw, lh, resp);
        sm->resp[tid] = resp;
    }
    __syncthreads();   // resp + (caller's) box/ar/mask visible

    // ===== Phase 2 FIRST: per-cell ciou + conf from registers =====
    if (active) {
        const int idx = cellBase + tid;
        int a = idx % 3;
        int r = idx / 3;
        int j = r % S; r /= S;
        int i = r % S;
        int b = r / S;

        float aw = c_anch[SCALE][a*2 + 0];
        float ah = c_anch[SCALE][a*2 + 1];

        float px = (sigmoidf(dx) + (float)j) * (float)STRIDE;
        float py = (sigmoidf(dy) + (float)i) * (float)STRIDE;
        float pw = ex2(dw * L2E) * aw;
        float ph = ex2(dh * L2E) * ah;

        float px1 = px - 0.5f*pw, py1 = py - 0.5f*ph;
        float px2 = px + 0.5f*pw, py2 = py + 0.5f*ph;
        float lx1 = lx - 0.5f*lw, ly1 = ly - 0.5f*lh;
        float lx2 = lx + 0.5f*lw, ly2 = ly + 0.5f*lh;

        float areap = (px2 - px1) * (py2 - py1);
        float areal = (lx2 - lx1) * (ly2 - ly1);
        float iw = fmaxf(fminf(px2, lx2) - fmaxf(px1, lx1), 0.f);
        float ih = fmaxf(fminf(py2, ly2) - fmaxf(py1, ly1), 0.f);
        float inter = iw * ih;
        float uni   = areap + areal - inter;
        float iou   = __fdividef(inter, uni + 1e-9f);

        float ew = fmaxf(px2, lx2) - fminf(px1, lx1);
        float eh = fmaxf(py2, ly2) - fminf(py1, ly1);
        float c2 = ew*ew + eh*eh;
        float ddx = px - lx, ddy = py - ly;
        float p2 = ddx*ddx + ddy*ddy;

        const float FOUR_OVER_PI2 = 0.40528473456935109f;
        float at = atanf(__fdividef(pw, ph + 1e-9f)) -
                   atanf(__fdividef(lw, lh + 1e-9f));
        float v     = FOUR_OVER_PI2 * at * at;
        float alpha = __fdividef(v, 1.f - iou + v);
        float ciou  = iou - __fdividef(p2, c2) - alpha * v;

        tc = resp * (2.f - lw*lh*INV_IN2) * (1.f - ciou);

        float pa = pw * ph;
        const float4* bptr = sm->box + b * NBOX;
        const float*  aptr = sm->ar  + b * NBOX;
        float m = -1e30f;
        #pragma unroll 5
        for (int k = 0; k < NBOX; k++) {
            float4 bx = bptr[k];
            float bw = fmaxf(fminf(px2, bx.z) - fmaxf(px1, bx.x), 0.f);
            float bh = fmaxf(fminf(py2, bx.w) - fmaxf(py1, bx.y), 0.f);
            m = fmaxf(m, __fmaf_rn(3.f, bw * bh, -aptr[k]));
        }

        float spc = softplusf(dc);
        tf = resp * (spc - dc);
        if (m < pa) tf += (1.f - resp) * spc;
    }

    // ===== Phase 1: coalesced float4 stream; product-form softplus =====
    const float4* __restrict__ cv4 = cv4g + (size_t)cellBase * CH / 4;
    const float4* __restrict__ lb4 = lb4g + (size_t)cellBase * CH / 4;
    const int nf4 = cells * CH / 4;

    #pragma unroll 8
    for (int t = tid; t < nf4; t += CPB) {
        const int e  = 4 * t;
        const int cl = e / CH;
        const int c0 = e - cl * CH;

        float4 x  = __ldg(cv4 + t);
        float4 lp = __ldg(lb4 + t);
        float4 mk = sm->mask[c0];
        float  rsp = sm->resp[cl];

        float t0 = ex2(x.x * L2E) * mk.x;
        float t1 = ex2(x.y * L2E) * mk.y;
        float t2 = ex2(x.z * L2E) * mk.z;
        float t3 = ex2(x.w * L2E) * mk.w;

        float p = (1.f + t0) * (1.f + t1) * (1.f + t2) * (1.f + t3);

        float dot = (lp.x * mk.x) * x.x
                  + (lp.y * mk.y) * x.y
                  + (lp.z * mk.z) * x.z
                  + (lp.w * mk.w) * x.w;

        ps += rsp * (LN2 * lg2(p) - dot);
    }
}

__global__ void __launch_bounds__(CPB)
yolo_fused_kernel(const float* __restrict__ conv_s, const float* __restrict__ lab_s,
                  const float* __restrict__ conv_m, const float* __restrict__ lab_m,
                  const float* __restrict__ conv_l, const float* __restrict__ lab_l,
                  const float* __restrict__ bboxes, float* __restrict__ out)
{
    __shared__ Smem sm;

    const int tid = threadIdx.x;

    for (int t = tid; t < NBATCH*NBOX; t += CPB) {
        float4 v = __ldg(reinterpret_cast<const float4*>(bboxes) + t);
        sm.box[t] = make_float4(v.x - 0.5f*v.z, v.y - 0.5f*v.w,
                                v.x + 0.5f*v.z, v.y + 0.5f*v.w);
        sm.ar[t]  = v.z * v.w;
    }
    if (tid < CH) {
        int c0 = tid;
        sm.mask[c0] = make_float4(
            (c0 >= 5)              ? 1.f : 0.f,
            (c0 >= 4 && c0 <= 83)  ? 1.f : 0.f,
            (c0 >= 3 && c0 <= 82)  ? 1.f : 0.f,
            (c0 >= 2 && c0 <= 81)  ? 1.f : 0.f);
    }
    // NOTE: __syncthreads happens inside process_scale (after head load)

    float tc = 0.f, tf = 0.f, ps = 0.f;

    const int blk = blockIdx.x;
    if (blk < BLKS_S) {
        process_scale<76,  8, 0, CELLS_S>(conv_s, lab_s, &sm, blk, tc, tf, ps);
    } else if (blk < BLKS_S + BLKS_M) {
        process_scale<38, 16, 1, CELLS_M>(conv_m, lab_m, &sm, blk - BLKS_S, tc, tf, ps);
    } else {
        process_scale<19, 32, 2, CELLS_L>(conv_l, lab_l, &sm, blk - BLKS_S - BLKS_M, tc, tf, ps);
    }

    // block reduction + device-wide finalize
    const unsigned mask = 0xffffffffu;
    #pragma unroll
    for (int off = 16; off; off >>= 1) {
        tc += __shfl_down_sync(mask, tc, off);
        tf += __shfl_down_sync(mask, tf, off);
        ps += __shfl_down_sync(mask, ps, off);
    }
    int wid = tid >> 5, lane = tid & 31;
    if (lane == 0) { sm.rbuf[0][wid] = tc; sm.rbuf[1][wid] = tf; sm.rbuf[2][wid] = ps; }
    __syncthreads();

    if (tid == 0) {
        float sc = 0.f, sf = 0.f, sp = 0.f;
        #pragma unroll
        for (int w = 0; w < CPB/32; w++) {
            sc += sm.rbuf[0][w]; sf += sm.rbuf[1][w]; sp += sm.rbuf[2][w];
        }
        atomicAdd(&g_acc[0], (double)sc);
        atomicAdd(&g_acc[1], (double)sf);
        atomicAdd(&g_acc[2], (double)sp);

        __threadfence();
        unsigned old = atomicInc(&g_count, NBLK - 1);
        if (old == NBLK - 1) {
            double ci = atomicAdd(&g_acc[0], 0.0) * (1.0 / NBATCH);
            double cf = atomicAdd(&g_acc[1], 0.0) * (1.0 / NBATCH);
            double pr = atomicAdd(&g_acc[2], 0.0) * (1.0 / NBATCH);
            out[0] = (float)(ci + cf + pr);
            out[1] = (float)ci;
            out[2] = (float)cf;
            out[3] = (float)pr;
            atomicExch((unsigned long long*)&g_acc[0], 0ULL);
            atomicExch((unsigned long long*)&g_acc[1], 0ULL);
            atomicExch((unsigned long long*)&g_acc[2], 0ULL);
        }
    }
}

extern "C" void kernel_launch(void* const* d_in, const int* in_sizes, int n_in,
                              void* d_out, int out_size)
{
    const float* conv_l = (const float*)d_in[0];
    const float* conv_m = (const float*)d_in[1];
    const float* conv_s = (const float*)d_in[2];
    const float* lab_s  = (const float*)d_in[3];
    const float* lab_m  = (const float*)d_in[4];
    const float* lab_l  = (const float*)d_in[5];
    const float* bb     = (const float*)d_in[6];

    yolo_fused_kernel<<<NBLK, CPB>>>(conv_s, lab_s, conv_m, lab_m,
                                     conv_l, lab_l, bb, (float*)d_out);
}

// round 12
// speedup vs baseline: 1.1496x; 1.0091x over previous
#include <cuda_runtime.h>
#include <math.h>

#define NCLS   80
#define CH     85
#define NBOX   70
#define NBATCH 16
#define CPB    256
#define INV_IN2 (1.0f/(608.0f*608.0f))

#define CELLS_S (NBATCH*76*76*3)   // 277248
#define CELLS_M (NBATCH*38*38*3)   //  69312
#define CELLS_L (NBATCH*19*19*3)   //  17328
#define BLKS_S  ((CELLS_S + CPB - 1) / CPB)   // 1083
#define BLKS_M  ((CELLS_M + CPB - 1) / CPB)   //  271
#define BLKS_L  ((CELLS_L + CPB - 1) / CPB)   //   68
#define NBLK    (BLKS_S + BLKS_M + BLKS_L)    // 1422

__device__ double   g_acc[3];
__device__ unsigned g_count;

__constant__ float c_anch[3][6] = {
    { 12.f,  16.f,  19.f,  36.f,  40.f,  28.f},
    { 36.f,  75.f,  76.f,  55.f,  72.f, 146.f},
    {142.f, 110.f, 192.f, 243.f, 459.f, 401.f}
};

__device__ __forceinline__ float ex2(float x) {
    float r; asm("ex2.approx.ftz.f32 %0, %1;" : "=f"(r) : "f"(x)); return r;
}
__device__ __forceinline__ float lg2(float x) {
    float r; asm("lg2.approx.ftz.f32 %0, %1;" : "=f"(r) : "f"(x)); return r;
}
#define L2E 1.4426950408889634f
#define LN2 0.6931471805599453f

__device__ __forceinline__ float softplusf(float x) {
    return fmaxf(x, 0.f) + LN2 * lg2(1.f + ex2(-fabsf(x) * L2E));
}
__device__ __forceinline__ float sigmoidf(float x) {
    return __fdividef(1.f, 1.f + ex2(-x * L2E));
}

struct Smem {
    float4 box [NBATCH*NBOX];
    float  ar  [NBATCH*NBOX];
    float4 mask[CH];          // per-c0 component masks (0/1)
    float  resp[CPB];         // label ch4 per local cell
    float  rbuf[3][CPB/32];
};

// branchless: h0..h4 = v[off..off+4]  (off in 0..3)
__device__ __forceinline__ void extract5_sel(
    float4 A, float4 B, int off,
    float& h0, float& h1, float& h2, float& h3, float& h4)
{
    float v0=A.x, v1=A.y, v2=A.z, v3=A.w, v4=B.x, v5=B.y, v6=B.z, v7=B.w;
    bool hi  = (off >= 2);
    bool odd = (off & 1);
    h0 = hi ? (odd ? v3 : v2) : (odd ? v1 : v0);
    h1 = hi ? (odd ? v4 : v3) : (odd ? v2 : v1);
    h2 = hi ? (odd ? v5 : v4) : (odd ? v3 : v2);
    h3 = hi ? (odd ? v6 : v5) : (odd ? v4 : v3);
    h4 = hi ? (odd ? v7 : v6) : (odd ? v5 : v4);
}

template<int S, int STRIDE, int SCALE, int NCELL>
__device__ __forceinline__ void process_scale(
    const float* __restrict__ conv,
    const float* __restrict__ label,
    Smem* sm, int sblk, float& tc, float& tf, float& ps)
{
    const int tid      = threadIdx.x;
    const int cellBase = sblk * CPB;
    const int cells    = min(CPB, NCELL - cellBase);
    const bool active  = (tid < cells);

    const float4* __restrict__ cv4g = reinterpret_cast<const float4*>(conv);
    const float4* __restrict__ lb4g = reinterpret_cast<const float4*>(label);

    // ===== Head load (vectorized, issued up-front; warms L2/L1 for phase 1) =====
    float dx=0.f, dy=0.f, dw=0.f, dh=0.f, dc=0.f;
    float lx=0.f, ly=0.f, lw=0.f, lh=0.f, resp=0.f;
    if (active) {
        const size_t f0 = (size_t)(cellBase + tid) * CH;
        const size_t q  = f0 >> 2;
        const int  off  = (int)(f0 & 3);
        float4 a0 = __ldg(cv4g + q), a1 = __ldg(cv4g + q + 1);
        float4 b0 = __ldg(lb4g + q), b1 = __ldg(lb4g + q + 1);
        extract5_sel(a0, a1, off, dx, dy, dw, dh, dc);
        extract5_sel(b0, b1, off, lx, ly, lw, lh, resp);
        sm->resp[tid] = resp;
    }
    __syncthreads();   // resp + (caller's) box/ar/mask visible

    // ===== Phase 2 FIRST: per-cell ciou + conf from registers =====
    if (active) {
        const int idx = cellBase + tid;
        int a = idx % 3;
        int r = idx / 3;
        int j = r % S; r /= S;
        int i = r % S;
        int b = r / S;

        float aw = c_anch[SCALE][a*2 + 0];
        float ah = c_anch[SCALE][a*2 + 1];

        float px = (sigmoidf(dx) + (float)j) * (float)STRIDE;
        float py = (sigmoidf(dy) + (float)i) * (float)STRIDE;
        float pw = ex2(dw * L2E) * aw;
        float ph = ex2(dh * L2E) * ah;

        float px1 = px - 0.5f*pw, py1 = py - 0.5f*ph;
        float px2 = px + 0.5f*pw, py2 = py + 0.5f*ph;
        float lx1 = lx - 0.5f*lw, ly1 = ly - 0.5f*lh;
        float lx2 = lx + 0.5f*lw, ly2 = ly + 0.5f*lh;

        float areap = (px2 - px1) * (py2 - py1);
        float areal = (lx2 - lx1) * (ly2 - ly1);
        float iw = fmaxf(fminf(px2, lx2) - fmaxf(px1, lx1), 0.f);
        float ih = fmaxf(fminf(py2, ly2) - fmaxf(py1, ly1), 0.f);
        float inter = iw * ih;
        float uni   = areap + areal - inter;
        float iou   = __fdividef(inter, uni + 1e-9f);

        float ew = fmaxf(px2, lx2) - fminf(px1, lx1);
        float eh = fmaxf(py2, ly2) - fminf(py1, ly1);
        float c2 = ew*ew + eh*eh;
        float ddx = px - lx, ddy = py - ly;
        float p2 = ddx*ddx + ddy*ddy;

        const float FOUR_OVER_PI2 = 0.40528473456935109f;
        float at = atanf(__fdividef(pw, ph + 1e-9f)) -
                   atanf(__fdividef(lw, lh + 1e-9f));
        float v     = FOUR_OVER_PI2 * at * at;
        float alpha = __fdividef(v, 1.f - iou + v);
        float ciou  = iou - __fdividef(p2, c2) - alpha * v;

        tc = resp * (2.f - lw*lh*INV_IN2) * (1.f - ciou);

        float pa = pw * ph;
        const float4* bptr = sm->box + b * NBOX;
        const float*  aptr = sm->ar  + b * NBOX;
        float m = -1e30f;
        #pragma unroll 5
        for (int k = 0; k < NBOX; k++) {
            float4 bx = bptr[k];
            float bw = fmaxf(fminf(px2, bx.z) - fmaxf(px1, bx.x), 0.f);
            float bh = fmaxf(fminf(py2, bx.w) - fmaxf(py1, bx.y), 0.f);
            m = fmaxf(m, __fmaf_rn(3.f, bw * bh, -aptr[k]));
        }

        float spc = softplusf(dc);
        tf = resp * (spc - dc);
        if (m < pa) tf += (1.f - resp) * spc;
    }

    // ===== Phase 1: coalesced float4 stream; product-form softplus =====
    const float4* __restrict__ cv4 = cv4g + (size_t)cellBase * CH / 4;
    const float4* __restrict__ lb4 = lb4g + (size_t)cellBase * CH / 4;
    const int nf4 = cells * CH / 4;

    #pragma unroll 8
    for (int t = tid; t < nf4; t += CPB) {
        const int e  = 4 * t;
        const int cl = e / CH;
        const int c0 = e - cl * CH;

        float4 x  = __ldg(cv4 + t);
        float4 lp = __ldg(lb4 + t);
        float4 mk = sm->mask[c0];
        float  rsp = sm->resp[cl];

        float t0 = ex2(x.x * L2E) * mk.x;
        float t1 = ex2(x.y * L2E) * mk.y;
        float t2 = ex2(x.z * L2E) * mk.z;
        float t3 = ex2(x.w * L2E) * mk.w;

        float p = (1.f + t0) * (1.f + t1) * (1.f + t2) * (1.f + t3);

        float dot = (lp.x * mk.x) * x.x
                  + (lp.y * mk.y) * x.y
                  + (lp.z * mk.z) * x.z
                  + (lp.w * mk.w) * x.w;

        ps += rsp * (LN2 * lg2(p) - dot);
    }
}

__global__ void __launch_bounds__(CPB, 3)
yolo_fused_kernel(const float* __restrict__ conv_s, const float* __restrict__ lab_s,
                  const float* __restrict__ conv_m, const float* __restrict__ lab_m,
                  const float* __restrict__ conv_l, const float* __restrict__ lab_l,
                  const float* __restrict__ bboxes, float* __restrict__ out)
{
    __shared__ Smem sm;

    const int tid = threadIdx.x;

    for (int t = tid; t < NBATCH*NBOX; t += CPB) {
        float4 v = __ldg(reinterpret_cast<const float4*>(bboxes) + t);
        sm.box[t] = make_float4(v.x - 0.5f*v.z, v.y - 0.5f*v.w,
                                v.x + 0.5f*v.z, v.y + 0.5f*v.w);
        sm.ar[t]  = v.z * v.w;
    }
    if (tid < CH) {
        int c0 = tid;
        sm.mask[c0] = make_float4(
            (c0 >= 5)              ? 1.f : 0.f,
            (c0 >= 4 && c0 <= 83)  ? 1.f : 0.f,
            (c0 >= 3 && c0 <= 82)  ? 1.f : 0.f,
            (c0 >= 2 && c0 <= 81)  ? 1.f : 0.f);
    }
    // NOTE: __syncthreads happens inside process_scale (after head load)

    float tc = 0.f, tf = 0.f, ps = 0.f;

    const int blk = blockIdx.x;
    if (blk < BLKS_S) {
        process_scale<76,  8, 0, CELLS_S>(conv_s, lab_s, &sm, blk, tc, tf, ps);
    } else if (blk < BLKS_S + BLKS_M) {
        process_scale<38, 16, 1, CELLS_M>(conv_m, lab_m, &sm, blk - BLKS_S, tc, tf, ps);
    } else {
        process_scale<19, 32, 2, CELLS_L>(conv_l, lab_l, &sm, blk - BLKS_S - BLKS_M, tc, tf, ps);
    }

    // block reduction + device-wide finalize
    const unsigned mask = 0xffffffffu;
    #pragma unroll
    for (int off = 16; off; off >>= 1) {
        tc += __shfl_down_sync(mask, tc, off);
        tf += __shfl_down_sync(mask, tf, off);
        ps += __shfl_down_sync(mask, ps, off);
    }
    int wid = tid >> 5, lane = tid & 31;
    if (lane == 0) { sm.rbuf[0][wid] = tc; sm.rbuf[1][wid] = tf; sm.rbuf[2][wid] = ps; }
    __syncthreads();

    if (tid == 0) {
        float sc = 0.f, sf = 0.f, sp = 0.f;
        #pragma unroll
        for (int w = 0; w < CPB/32; w++) {
            sc += sm.rbuf[0][w]; sf += sm.rbuf[1][w]; sp += sm.rbuf[2][w];
        }
        atomicAdd(&g_acc[0], (double)sc);
        atomicAdd(&g_acc[1], (double)sf);
        atomicAdd(&g_acc[2], (double)sp);

        __threadfence();
        unsigned old = atomicInc(&g_count, NBLK - 1);
        if (old == NBLK - 1) {
            double ci = atomicAdd(&g_acc[0], 0.0) * (1.0 / NBATCH);
            double cf = atomicAdd(&g_acc[1], 0.0) * (1.0 / NBATCH);
            double pr = atomicAdd(&g_acc[2], 0.0) * (1.0 / NBATCH);
            out[0] = (float)(ci + cf + pr);
            out[1] = (float)ci;
            out[2] = (float)cf;
            out[3] = (float)pr;
            atomicExch((unsigned long long*)&g_acc[0], 0ULL);
            atomicExch((unsigned long long*)&g_acc[1], 0ULL);
            atomicExch((unsigned long long*)&g_acc[2], 0ULL);
        }
    }
}

extern "C" void kernel_launch(void* const* d_in, const int* in_sizes, int n_in,
                              void* d_out, int out_size)
{
    const float* conv_l = (const float*)d_in[0];
    const float* conv_m = (const float*)d_in[1];
    const float* conv_s = (const float*)d_in[2];
    const float* lab_s  = (const float*)d_in[3];
    const float* lab_m  = (const float*)d_in[4];
    const float* lab_l  = (const float*)d_in[5];
    const float* bb     = (const float*)d_in[6];

    yolo_fused_kernel<<<NBLK, CPB>>>(conv_s, lab_s, conv_m, lab_m,
                                     conv_l, lab_l, bb, (float*)d_out);
}

// round 14
// speedup vs baseline: 1.1929x; 1.0377x over previous
#include <cuda_runtime.h>
#include <cstdint>
#include <math.h>

#define NCLS   80
#define CH     85
#define NBOX   70
#define NBATCH 16
#define CPB    256
#define DST    4            // cp.async pipeline depth (power of 2)
#define INV_IN2 (1.0f/(608.0f*608.0f))

#define CELLS_S (NBATCH*76*76*3)   // 277248
#define CELLS_M (NBATCH*38*38*3)   //  69312
#define CELLS_L (NBATCH*19*19*3)   //  17328
#define BLKS_S  ((CELLS_S + CPB - 1) / CPB)   // 1083
#define BLKS_M  ((CELLS_M + CPB - 1) / CPB)   //  271
#define BLKS_L  ((CELLS_L + CPB - 1) / CPB)   //   68
#define NBLK    (BLKS_S + BLKS_M + BLKS_L)    // 1422

__device__ double   g_acc[3];
__device__ unsigned g_count;

__constant__ float c_anch[3][6] = {
    { 12.f,  16.f,  19.f,  36.f,  40.f,  28.f},
    { 36.f,  75.f,  76.f,  55.f,  72.f, 146.f},
    {142.f, 110.f, 192.f, 243.f, 459.f, 401.f}
};

__device__ __forceinline__ float ex2(float x) {
    float r; asm("ex2.approx.ftz.f32 %0, %1;" : "=f"(r) : "f"(x)); return r;
}
__device__ __forceinline__ float lg2(float x) {
    float r; asm("lg2.approx.ftz.f32 %0, %1;" : "=f"(r) : "f"(x)); return r;
}
#define L2E 1.4426950408889634f
#define LN2 0.6931471805599453f

__device__ __forceinline__ float softplusf(float x) {
    return fmaxf(x, 0.f) + LN2 * lg2(1.f + ex2(-fabsf(x) * L2E));
}
__device__ __forceinline__ float sigmoidf(float x) {
    return __fdividef(1.f, 1.f + ex2(-x * L2E));
}

struct Smem {
    float4 cbuf[DST][CPB];     // conv staging ring (16 KB)
    float4 lbuf[DST][CPB];     // label staging ring (16 KB)
    float4 box [2*NBOX];       // corners for the <=2 batches this block touches
    float  ar  [2*NBOX];
    float4 mask[CH];           // per-c0 component masks (0/1)
    float  resp[CPB];
    float  rbuf[3][CPB/32];
};

// branchless: h0..h4 = v[off..off+4]  (off in 0..3)
__device__ __forceinline__ void extract5_sel(
    float4 A, float4 B, int off,
    float& h0, float& h1, float& h2, float& h3, float& h4)
{
    float v0=A.x, v1=A.y, v2=A.z, v3=A.w, v4=B.x, v5=B.y, v6=B.z, v7=B.w;
    bool hi  = (off >= 2);
    bool odd = (off & 1);
    h0 = hi ? (odd ? v3 : v2) : (odd ? v1 : v0);
    h1 = hi ? (odd ? v4 : v3) : (odd ? v2 : v1);
    h2 = hi ? (odd ? v5 : v4) : (odd ? v3 : v2);
    h3 = hi ? (odd ? v6 : v5) : (odd ? v4 : v3);
    h4 = hi ? (odd ? v7 : v6) : (odd ? v5 : v4);
}

template<int S, int STRIDE, int SCALE, int NCELL>
__device__ __forceinline__ void process_scale(
    const float* __restrict__ conv,
    const float* __restrict__ label,
    const float4* __restrict__ bbox4,
    Smem* sm, int sblk, float& tc, float& tf, float& ps)
{
    const int tid      = threadIdx.x;
    const int cellBase = sblk * CPB;
    const int cells    = min(CPB, NCELL - cellBase);
    const bool active  = (tid < cells);
    const int bmin     = cellBase / (S*S*3);

    const float4* __restrict__ cv4g = reinterpret_cast<const float4*>(conv);
    const float4* __restrict__ lb4g = reinterpret_cast<const float4*>(label);

    // ----- stage true-bbox corners for batches bmin, bmin+1 -----
    if (tid < 2*NBOX) {
        int bb = bmin + (tid >= NBOX ? 1 : 0);
        if (bb > NBATCH-1) bb = NBATCH-1;
        int k  = tid >= NBOX ? tid - NBOX : tid;
        float4 v = __ldg(bbox4 + bb*NBOX + k);
        sm->box[tid] = make_float4(v.x - 0.5f*v.z, v.y - 0.5f*v.w,
                                   v.x + 0.5f*v.z, v.y + 0.5f*v.w);
        sm->ar[tid]  = v.z * v.w;
    }

    // ----- head load (vectorized LDG; .ca path, warms L1) -----
    float dx=0.f, dy=0.f, dw=0.f, dh=0.f, dc=0.f;
    float lx=0.f, ly=0.f, lw=0.f, lh=0.f, resp=0.f;
    if (active) {
        const size_t f0 = (size_t)(cellBase + tid) * CH;
        const size_t q  = f0 >> 2;
        const int  off  = (int)(f0 & 3);
        float4 a0 = __ldg(cv4g + q), a1 = __ldg(cv4g + q + 1);
        float4 b0 = __ldg(lb4g + q), b1 = __ldg(lb4g + q + 1);
        extract5_sel(a0, a1, off, dx, dy, dw, dh, dc);
        extract5_sel(b0, b1, off, lx, ly, lw, lh, resp);
        sm->resp[tid] = resp;
    }

    // ----- cp.async pipeline (each thread stages/consumes ONLY its own 16B) -----
    const float4* __restrict__ cv4 = cv4g + (size_t)cellBase * CH / 4;
    const float4* __restrict__ lb4 = lb4g + (size_t)cellBase * CH / 4;
    const int nf4   = cells * CH / 4;
    const int nIter = (nf4 + CPB - 1) / CPB;

    auto issue_stage = [&](int k) {
        int t = k * CPB + tid;
        if (t < nf4) {
            unsigned int ca = (unsigned int)__cvta_generic_to_shared(&sm->cbuf[k & (DST-1)][tid]);
            unsigned int la = (unsigned int)__cvta_generic_to_shared(&sm->lbuf[k & (DST-1)][tid]);
            asm volatile("cp.async.cg.shared.global [%0], [%1], 16;"
                         :: "r"(ca), "l"((const void*)(cv4 + t)) : "memory");
            asm volatile("cp.async.cg.shared.global [%0], [%1], 16;"
                         :: "r"(la), "l"((const void*)(lb4 + t)) : "memory");
        }
        asm volatile("cp.async.commit_group;" ::: "memory");
    };

    // prologue: DST-1 stages in flight before phase 2 compute
    #pragma unroll
    for (int k = 0; k < DST-1; k++) issue_stage(k);

    __syncthreads();   // resp + box/ar (+ caller's mask) visible

    // ===== Phase 2: per-cell ciou + conf from registers (overlaps prologue) =====
    if (active) {
        const int idx = cellBase + tid;
        int a = idx % 3;
        int r = idx / 3;
        int j = r % S; r /= S;
        int i = r % S;
        int b = r / S;

        float aw = c_anch[SCALE][a*2 + 0];
        float ah = c_anch[SCALE][a*2 + 1];

        float px = (sigmoidf(dx) + (float)j) * (float)STRIDE;
        float py = (sigmoidf(dy) + (float)i) * (float)STRIDE;
        float pw = ex2(dw * L2E) * aw;
        float ph = ex2(dh * L2E) * ah;

        float px1 = px - 0.5f*pw, py1 = py - 0.5f*ph;
        float px2 = px + 0.5f*pw, py2 = py + 0.5f*ph;
        float lx1 = lx - 0.5f*lw, ly1 = ly - 0.5f*lh;
        float lx2 = lx + 0.5f*lw, ly2 = ly + 0.5f*lh;

        float areap = (px2 - px1) * (py2 - py1);
        float areal = (lx2 - lx1) * (ly2 - ly1);
        float iw = fmaxf(fminf(px2, lx2) - fmaxf(px1, lx1), 0.f);
        float ih = fmaxf(fminf(py2, ly2) - fmaxf(py1, ly1), 0.f);
        float inter = iw * ih;
        float uni   = areap + areal - inter;
        float iou   = __fdividef(inter, uni + 1e-9f);

        float ew = fmaxf(px2, lx2) - fminf(px1, lx1);
        float eh = fmaxf(py2, ly2) - fminf(py1, ly1);
        float c2 = ew*ew + eh*eh;
        float ddx = px - lx, ddy = py - ly;
        float p2 = ddx*ddx + ddy*ddy;

        const float FOUR_OVER_PI2 = 0.40528473456935109f;
        float at = atanf(__fdividef(pw, ph + 1e-9f)) -
                   atanf(__fdividef(lw, lh + 1e-9f));
        float v     = FOUR_OVER_PI2 * at * at;
        float alpha = __fdividef(v, 1.f - iou + v);
        float ciou  = iou - __fdividef(p2, c2) - alpha * v;

        tc = resp * (2.f - lw*lh*INV_IN2) * (1.f - ciou);

        float pa = pw * ph;
        const float4* bptr = sm->box + (b - bmin) * NBOX;
        const float*  aptr = sm->ar  + (b - bmin) * NBOX;
        float m = -1e30f;
        #pragma unroll 5
        for (int k = 0; k < NBOX; k++) {
            float4 bx = bptr[k];
            float bw = fmaxf(fminf(px2, bx.z) - fmaxf(px1, bx.x), 0.f);
            float bh = fmaxf(fminf(py2, bx.w) - fmaxf(py1, bx.y), 0.f);
            m = fmaxf(m, __fmaf_rn(3.f, bw * bh, -aptr[k]));
        }

        float spc = softplusf(dc);
        tf = resp * (spc - dc);
        if (m < pa) tf += (1.f - resp) * spc;
    }

    // ===== Phase 1: smem-staged stream; product-form softplus =====
    for (int k = 0; k < nIter; k++) {
        issue_stage(k + DST - 1);
        asm volatile("cp.async.wait_group %0;" :: "n"(DST-1) : "memory");

        int t = k * CPB + tid;
        if (t < nf4) {
            const int e  = 4 * t;
            const int cl = e / CH;
            const int c0 = e - cl * CH;

            float4 x  = sm->cbuf[k & (DST-1)][tid];
            float4 lp = sm->lbuf[k & (DST-1)][tid];
            float4 mk = sm->mask[c0];
            float  rsp = sm->resp[cl];

            float t0 = ex2(x.x * L2E) * mk.x;
            float t1 = ex2(x.y * L2E) * mk.y;
            float t2 = ex2(x.z * L2E) * mk.z;
            float t3 = ex2(x.w * L2E) * mk.w;

            float p = (1.f + t0) * (1.f + t1) * (1.f + t2) * (1.f + t3);

            float dot = (lp.x * mk.x) * x.x
                      + (lp.y * mk.y) * x.y
                      + (lp.z * mk.z) * x.z
                      + (lp.w * mk.w) * x.w;

            ps += rsp * (LN2 * lg2(p) - dot);
        }
    }
}

__global__ void __launch_bounds__(CPB, 5)
yolo_fused_kernel(const float* __restrict__ conv_s, const float* __restrict__ lab_s,
                  const float* __restrict__ conv_m, const float* __restrict__ lab_m,
                  const float* __restrict__ conv_l, const float* __restrict__ lab_l,
                  const float* __restrict__ bboxes, float* __restrict__ out)
{
    __shared__ Smem sm;

    const int tid = threadIdx.x;
    const float4* bbox4 = reinterpret_cast<const float4*>(bboxes);

    if (tid < CH) {
        int c0 = tid;
        sm.mask[c0] = make_float4(
            (c0 >= 5)              ? 1.f : 0.f,
            (c0 >= 4 && c0 <= 83)  ? 1.f : 0.f,
            (c0 >= 3 && c0 <= 82)  ? 1.f : 0.f,
            (c0 >= 2 && c0 <= 81)  ? 1.f : 0.f);
    }
    // NOTE: __syncthreads happens inside process_scale

    float tc = 0.f, tf = 0.f, ps = 0.f;

    const int blk = blockIdx.x;
    if (blk < BLKS_S) {
        process_scale<76,  8, 0, CELLS_S>(conv_s, lab_s, bbox4, &sm, blk, tc, tf, ps);
    } else if (blk < BLKS_S + BLKS_M) {
        process_scale<38, 16, 1, CELLS_M>(conv_m, lab_m, bbox4, &sm, blk - BLKS_S, tc, tf, ps);
    } else {
        process_scale<19, 32, 2, CELLS_L>(conv_l, lab_l, bbox4, &sm, blk - BLKS_S - BLKS_M, tc, tf, ps);
    }

    // block reduction + device-wide finalize
    const unsigned mask = 0xffffffffu;
    #pragma unroll
    for (int off = 16; off; off >>= 1) {
        tc += __shfl_down_sync(mask, tc, off);
        tf += __shfl_down_sync(mask, tf, off);
        ps += __shfl_down_sync(mask, ps, off);
    }
    int wid = tid >> 5, lane = tid & 31;
    if (lane == 0) { sm.rbuf[0][wid] = tc; sm.rbuf[1][wid] = tf; sm.rbuf[2][wid] = ps; }
    __syncthreads();

    if (tid == 0) {
        float sc = 0.f, sf = 0.f, sp = 0.f;
        #pragma unroll
        for (int w = 0; w < CPB/32; w++) {
            sc += sm.rbuf[0][w]; sf += sm.rbuf[1][w]; sp += sm.rbuf[2][w];
        }
        atomicAdd(&g_acc[0], (double)sc);
        atomicAdd(&g_acc[1], (double)sf);
        atomicAdd(&g_acc[2], (double)sp);

        __threadfence();
        unsigned old = atomicInc(&g_count, NBLK - 1);
        if (old == NBLK - 1) {
            double ci = atomicAdd(&g_acc[0], 0.0) * (1.0 / NBATCH);
            double cf = atomicAdd(&g_acc[1], 0.0) * (1.0 / NBATCH);
            double pr = atomicAdd(&g_acc[2], 0.0) * (1.0 / NBATCH);
            out[0] = (float)(ci + cf + pr);
            out[1] = (float)ci;
            out[2] = (float)cf;
            out[3] = (float)pr;
            atomicExch((unsigned long long*)&g_acc[0], 0ULL);
            atomicExch((unsigned long long*)&g_acc[1], 0ULL);
            atomicExch((unsigned long long*)&g_acc[2], 0ULL);
        }
    }
}

extern "C" void kernel_launch(void* const* d_in, const int* in_sizes, int n_in,
                              void* d_out, int out_size)
{
    const float* conv_l = (const float*)d_in[0];
    const float* conv_m = (const float*)d_in[1];
    const float* conv_s = (const float*)d_in[2];
    const float* lab_s  = (const float*)d_in[3];
    const float* lab_m  = (const float*)d_in[4];
    const float* lab_l  = (const float*)d_in[5];
    const float* bb     = (const float*)d_in[6];

    yolo_fused_kernel<<<NBLK, CPB>>>(conv_s, lab_s, conv_m, lab_m,
                                     conv_l, lab_l, bb, (float*)d_out);
}